// round 7
// baseline (speedup 1.0000x reference)
#include <cuda_runtime.h>
#include <cstdint>
#include <cstddef>

// Fixed shapes: B=1, N=1000, T=256, D=512, M=258, NUM=10
// out row = 3082 floats (12328 B; 16B-aligned only for even n)
#define N_CAND   1000
#define T_DIM    256
#define D_DIM    512
#define M_DIM    258
#define NUMF     10
#define ROW_OUT  3082

// Two blocks per candidate (3 sections each), 128 threads per block.
// Each thread: 3 independent LDG.128 (front-batched), then 3 stores.
// Section order in the output row:
//   0: blo[c1]  1: blo[c2]  2: blo[c4]  3: blo[c5]  4: att[c0+2]  5: att[c3+2]
__global__ __launch_bounds__(128) void feature_gather_fine(
    const int* __restrict__ cand,        // [N,6]
    const float* __restrict__ num,       // [N,10]
    const float* __restrict__ blo,       // [N,T,D]
    const float* __restrict__ att,       // [N,M,D]
    float* __restrict__ out)             // [N,3082]
{
    const int n    = blockIdx.x >> 1;
    const int half = blockIdx.x & 1;     // 0: sections 0..2, 1: sections 3..5
    const int lane = threadIdx.x;        // 0..127 (float4 lane within a section)

    // Candidate indices (L1 broadcast).
    const int2* cp = (const int2*)(cand + n * 6);
    const int2 p01 = __ldg(cp + 0);      // c0, c1
    const int2 p23 = __ldg(cp + 1);      // c2, c3
    const int2 p45 = __ldg(cp + 2);      // c4, c5

    const float4* b4 = (const float4*)(blo + (size_t)n * T_DIM * D_DIM);
    const float4* a4 = (const float4*)(att + (size_t)n * M_DIM * D_DIM);
    const int R4 = D_DIM / 4;            // 128 float4 per row

    float4 v0, v1, v2;
    if (half == 0) {
        // sections 0,1,2 : blo[c1], blo[c2], blo[c4]
        v0 = __ldg(b4 + (size_t)p01.y * R4 + lane);
        v1 = __ldg(b4 + (size_t)p23.x * R4 + lane);
        v2 = __ldg(b4 + (size_t)p45.x * R4 + lane);
    } else {
        // sections 3,4,5 : blo[c5], att[c0+2], att[c3+2]
        v0 = __ldg(b4 + (size_t)p45.y * R4 + lane);
        v1 = __ldg(a4 + (size_t)(p01.x + 2) * R4 + lane);
        v2 = __ldg(a4 + (size_t)(p23.y + 2) * R4 + lane);
    }

    float* outRow = out + (size_t)n * ROW_OUT;
    const int s0 = half * 3;

    if ((n & 1) == 0) {
        // 16B-aligned output row: streaming float4 stores.
        float4* o4 = (float4*)outRow;
        float4* d0 = o4 + (s0 + 0) * R4 + lane;
        float4* d1 = o4 + (s0 + 1) * R4 + lane;
        float4* d2 = o4 + (s0 + 2) * R4 + lane;
        asm volatile("st.global.cs.v4.f32 [%0], {%1,%2,%3,%4};"
                     :: "l"(d0), "f"(v0.x), "f"(v0.y), "f"(v0.z), "f"(v0.w) : "memory");
        asm volatile("st.global.cs.v4.f32 [%0], {%1,%2,%3,%4};"
                     :: "l"(d1), "f"(v1.x), "f"(v1.y), "f"(v1.z), "f"(v1.w) : "memory");
        asm volatile("st.global.cs.v4.f32 [%0], {%1,%2,%3,%4};"
                     :: "l"(d2), "f"(v2.x), "f"(v2.y), "f"(v2.z), "f"(v2.w) : "memory");
    } else {
        // 8B-aligned output row: float2 stores.
        float2* o2 = (float2*)outRow;
        const int i0 = ((s0 + 0) * R4 + lane) * 2;
        const int i1 = ((s0 + 1) * R4 + lane) * 2;
        const int i2 = ((s0 + 2) * R4 + lane) * 2;
        o2[i0]     = make_float2(v0.x, v0.y);
        o2[i0 + 1] = make_float2(v0.z, v0.w);
        o2[i1]     = make_float2(v1.x, v1.y);
        o2[i1 + 1] = make_float2(v1.z, v1.w);
        o2[i2]     = make_float2(v2.x, v2.y);
        o2[i2 + 1] = make_float2(v2.z, v2.w);
    }

    // Numeric features: handled once per candidate by the half==1 block.
    if (half == 1 && lane < NUMF / 2) {
        const float2* num2 = (const float2*)(num + (size_t)n * NUMF);
        ((float2*)outRow)[6 * (D_DIM / 2) + lane] = __ldg(num2 + lane);
    }
}

extern "C" void kernel_launch(void* const* d_in, const int* in_sizes, int n_in,
                              void* d_out, int out_size) {
    const int*   cand = (const int*)d_in[0];
    const float* num  = (const float*)d_in[1];
    const float* blo  = (const float*)d_in[2];
    const float* att  = (const float*)d_in[3];
    float* out = (float*)d_out;

    feature_gather_fine<<<N_CAND * 2, 128>>>(cand, num, blo, att, out);
}